// round 9
// baseline (speedup 1.0000x reference)
#include <cuda_runtime.h>
#include <math.h>

#define PH 7
#define PW 7
#define NC 256
#define MAXR 1024

// Per-ROI params: A = {x1s, y1s, bin_w, bin_h}, B = {H, baseoff, lvl, 0}
__device__ float4 g_params_a[MAXR];
__device__ int4   g_params_b[MAXR];

__global__ void prep_kernel(const float* __restrict__ boxes, int R)
{
    int r = blockIdx.x * blockDim.x + threadIdx.x;
    if (r >= R) return;

    float bx1 = boxes[r * 4 + 0];
    float by1 = boxes[r * 4 + 1];
    float bx2 = boxes[r * 4 + 2];
    float by2 = boxes[r * 4 + 3];

    float area = (bx2 - bx1) * (by2 - by1);
    float s = sqrtf(area);
    float lf = floorf(4.0f + log2f(s / 224.0f + 1e-6f));
    lf = fminf(fmaxf(lf, 2.0f), 5.0f);
    int lvl = (int)lf - 2;

    int H; float scale;
    switch (lvl) {
        case 0:  H = 200; scale = 0.25f;    break;
        case 1:  H = 100; scale = 0.125f;   break;
        case 2:  H = 50;  scale = 0.0625f;  break;
        default: H = 25;  scale = 0.03125f; break;
    }

    int bidx = (2 * r) / R;                 // B=2
    int baseoff = bidx * NC * H * H;

    float x1s = bx1 * scale, y1s = by1 * scale;
    float roi_w = fmaxf(bx2 * scale - x1s, 1.0f);
    float roi_h = fmaxf(by2 * scale - y1s, 1.0f);

    g_params_a[r] = make_float4(x1s, y1s, roi_w * (1.0f / PW), roi_h * (1.0f / PH));
    g_params_b[r] = make_int4(H, baseoff, lvl, 0);
}

// Block = (roi, ph); warp w = channels [w*32, w*32+32).
// Lanes 0..27 = (pw, sx, xtap) tap x-positions along the bin row.
// The 2 y-samples need up to 4 feature rows; duplicates are folded:
//   yl0==yl1           -> 2 row loads (small ROIs, bin_h < 1)
//   yh0==yl1           -> 3 row loads (common)
//   otherwise          -> 4 row loads
// 4-lane shfl reduction finishes each bin.
__global__ void __launch_bounds__(256, 5) pooler_kernel(
    const float* __restrict__ x0, const float* __restrict__ x1,
    const float* __restrict__ x2, const float* __restrict__ x3,
    float* __restrict__ out, int R)
{
    int bid  = blockIdx.x;
    int r    = bid / PH;
    int ph   = bid - r * PH;
    int warp = threadIdx.x >> 5;
    int lane = threadIdx.x & 31;

    float4 pa = g_params_a[r];
    int4   pb = g_params_b[r];
    float x1s = pa.x, y1s = pa.y, bin_w = pa.z, bin_h = pa.w;
    int H = pb.x, baseoff = pb.y, lvl = pb.z;
    int W = H;
    size_t HW = (size_t)H * W;

    const float* feat = (lvl == 0) ? x0 : (lvl == 1) ? x1 : (lvl == 2) ? x2 : x3;

    // y geometry for this ph: 2 samples -> up to 4 rows (uniform across warp)
    int   off[4];
    float wy[4];
    #pragma unroll
    for (int sy = 0; sy < 2; sy++) {
        float y = y1s + ph * bin_h + (sy + 0.5f) * bin_h * 0.5f;
        bool ye = (y < -1.0f) || (y > (float)H);
        float yc = fmaxf(y, 0.0f);
        float yl0 = floorf(yc);
        int yl_, yh_; float l;
        if (yl0 >= (float)(H - 1)) { yl_ = H - 1; yh_ = H - 1; l = 0.0f; }
        else { yl_ = (int)yl0; yh_ = yl_ + 1; l = yc - yl0; }
        off[2 * sy + 0] = yl_ * W;
        off[2 * sy + 1] = yh_ * W;
        wy[2 * sy + 0] = ye ? 0.0f : (1.0f - l);
        wy[2 * sy + 1] = ye ? 0.0f : l;
    }
    // dedup rows (warp-uniform)
    int nrows;
    if (off[0] == off[2]) {                 // both samples in same cell pair
        wy[0] += wy[2]; wy[1] += wy[3];
        nrows = 2;
    } else if (off[1] == off[2]) {          // shared middle row
        wy[1] += wy[2]; off[2] = off[3]; wy[2] = wy[3];
        nrows = 3;
    } else {
        nrows = 4;
    }

    // lane x geometry: lane = pw*4 + sx*2 + xtap (28 active)
    int pw = lane >> 2;
    int sx = (lane >> 1) & 1;
    int xt = lane & 1;
    float wx = 0.0f;
    int xoff = 0;
    if (lane < 28) {
        float x = x1s + pw * bin_w + (sx + 0.5f) * bin_w * 0.5f;
        bool xe = (x < -1.0f) || (x > (float)W);
        float xc = fmaxf(x, 0.0f);
        float xl0 = floorf(xc);
        int xl_, xh_; float l;
        if (xl0 >= (float)(W - 1)) { xl_ = W - 1; xh_ = W - 1; l = 0.0f; }
        else { xl_ = (int)xl0; xh_ = xl_ + 1; l = xc - xl0; }
        xoff = xt ? xh_ : xl_;
        wx = xe ? 0.0f : (xt ? l : (1.0f - l)) * 0.25f;   // fold 2x2 mean
    }

    int c0 = warp * 32;
    const float* base = feat + baseoff + (size_t)c0 * HW + xoff;
    bool writer = ((lane & 3) == 0) && (lane < 28);
    size_t obase = ((size_t)r * NC + c0) * (PH * PW) + ph * PW + pw;

    float w0 = wx * wy[0], w1 = wx * wy[1], w2 = wx * wy[2], w3 = wx * wy[3];

    if (nrows == 2) {
        const float* p0 = base + off[0];
        const float* p1 = base + off[1];
        #pragma unroll 4
        for (int k = 0; k < 32; k++) {
            float v = w0 * __ldg(p0) + w1 * __ldg(p1);
            v += __shfl_xor_sync(0xffffffffu, v, 1);
            v += __shfl_xor_sync(0xffffffffu, v, 2);
            if (writer) out[obase + (size_t)k * (PH * PW)] = v;
            p0 += HW; p1 += HW;
        }
    } else if (nrows == 3) {
        const float* p0 = base + off[0];
        const float* p1 = base + off[1];
        const float* p2 = base + off[2];
        #pragma unroll 4
        for (int k = 0; k < 32; k++) {
            float v = w0 * __ldg(p0) + w1 * __ldg(p1) + w2 * __ldg(p2);
            v += __shfl_xor_sync(0xffffffffu, v, 1);
            v += __shfl_xor_sync(0xffffffffu, v, 2);
            if (writer) out[obase + (size_t)k * (PH * PW)] = v;
            p0 += HW; p1 += HW; p2 += HW;
        }
    } else {
        const float* p0 = base + off[0];
        const float* p1 = base + off[1];
        const float* p2 = base + off[2];
        const float* p3 = base + off[3];
        #pragma unroll 4
        for (int k = 0; k < 32; k++) {
            float v = w0 * __ldg(p0) + w1 * __ldg(p1)
                    + w2 * __ldg(p2) + w3 * __ldg(p3);
            v += __shfl_xor_sync(0xffffffffu, v, 1);
            v += __shfl_xor_sync(0xffffffffu, v, 2);
            if (writer) out[obase + (size_t)k * (PH * PW)] = v;
            p0 += HW; p1 += HW; p2 += HW; p3 += HW;
        }
    }
}

extern "C" void kernel_launch(void* const* d_in, const int* in_sizes, int n_in,
                              void* d_out, int out_size) {
    const float* x0    = (const float*)d_in[0];
    const float* x1    = (const float*)d_in[1];
    const float* x2    = (const float*)d_in[2];
    const float* x3    = (const float*)d_in[3];
    const float* boxes = (const float*)d_in[4];
    float* out = (float*)d_out;

    int R = in_sizes[4] / 4;    // B*N = 1024
    prep_kernel<<<(R + 255) / 256, 256>>>(boxes, R);
    pooler_kernel<<<R * PH, 256>>>(x0, x1, x2, x3, out, R);
}